// round 5
// baseline (speedup 1.0000x reference)
#include <cuda_runtime.h>

#define BB   4
#define CC   256
#define HH   64
#define WW   64
#define HWS  4096         // H*W
#define NP   9            // kernel points
#define OCH  18           // offset channels
#define OPL  256          // out planes
#define KTOT 2304         // C*9

#define MT   64           // GEMM M tile (positions per block) == one image row
#define CCK  4            // channels per K chunk
#define KC   36           // K per chunk = CCK*9
#define NTH  288          // 9 warps: 576 (k,posl) pairs = 2 per thread
#define SB_STRIDE 260     // padded B row stride (floats)

// sampling metadata scratch
__device__ float4 g_mw[BB * HWS * NP];
__device__ int4   g_mi[BB * HWS * NP];
// transposed conv weights: g_wT[kg][o], kg = c*9+k  (2.36 MB, L2-resident)
__device__ float  g_wT[KTOT * OPL];

// ---------------------------------------------------------------------------
// packed fp32 + async-copy helpers
// ---------------------------------------------------------------------------
__device__ __forceinline__ unsigned long long dup2(float v) {
    unsigned long long r;
    asm("mov.b64 %0, {%1, %1};" : "=l"(r) : "f"(v));
    return r;
}
__device__ __forceinline__ void fma2(unsigned long long& acc,
                                     unsigned long long a, unsigned long long b) {
    asm("fma.rn.f32x2 %0, %1, %2, %0;" : "+l"(acc) : "l"(a), "l"(b));
}
union UPair { unsigned long long u; float2 f; };

__device__ __forceinline__ void cpa16(float* dst, const float* src) {
    unsigned s = (unsigned)__cvta_generic_to_shared(dst);
    asm volatile("cp.async.cg.shared.global [%0], [%1], 16;" :: "r"(s), "l"(src));
}
__device__ __forceinline__ void cpa_commit() { asm volatile("cp.async.commit_group;"); }
__device__ __forceinline__ void cpa_wait()   { asm volatile("cp.async.wait_group 0;"); }

// ---------------------------------------------------------------------------
// Kernel 1 (fused): blocks [0,128): offset conv + sampling metadata
//                   blocks [128,2432): w_conv transpose
// ---------------------------------------------------------------------------
__global__ __launch_bounds__(256) void prep_kernel(const float* __restrict__ x,
                                                   const float* __restrict__ w_p,
                                                   const float* __restrict__ wc)
{
    if (blockIdx.x >= 128) {
        int idx = (blockIdx.x - 128) * 256 + threadIdx.x;
        if (idx < KTOT * OPL) {
            int kg = idx >> 8;
            int o  = idx & 255;
            g_wT[idx] = wc[o * KTOT + kg];
        }
        return;
    }

    __shared__ float s_wp[32][OCH][12];

    const int tid = threadIdx.x;
    const int pos = blockIdx.x * 128 + (tid & 127);
    const int b = pos >> 12;
    const int h = (pos >> 6) & 63;
    const int w = pos & 63;
    const bool active = tid < 128;

    float acc[OCH];
#pragma unroll
    for (int i = 0; i < OCH; i++) acc[i] = 0.f;

    const float* xb = x + (size_t)b * CC * HWS;

    for (int c0 = 0; c0 < CC; c0 += 32) {
        __syncthreads();
        for (int i = tid; i < 32 * OCH * 9; i += 256) {
            int cl = i / (OCH * 9);
            int r  = i % (OCH * 9);
            int o  = r / 9;
            int t  = r % 9;
            s_wp[cl][o][t] = w_p[(o * CC + c0 + cl) * 9 + t];
        }
        __syncthreads();

        if (active) {
            for (int cl = 0; cl < 32; cl++) {
                const float* xp = xb + (c0 + cl) * HWS;
                float xv[9];
#pragma unroll
                for (int dh = -1; dh <= 1; dh++) {
#pragma unroll
                    for (int dw = -1; dw <= 1; dw++) {
                        int hh = h + dh, ww = w + dw;
                        float v = 0.f;
                        if (hh >= 0 && hh < HH && ww >= 0 && ww < WW) v = xp[hh * WW + ww];
                        xv[(dh + 1) * 3 + (dw + 1)] = v;
                    }
                }
#pragma unroll
                for (int o = 0; o < OCH; o++) {
                    float4 wa = *(const float4*)&s_wp[cl][o][0];
                    float4 wb = *(const float4*)&s_wp[cl][o][4];
                    float  w8 = s_wp[cl][o][8];
                    acc[o] += wa.x * xv[0] + wa.y * xv[1] + wa.z * xv[2] + wa.w * xv[3]
                            + wb.x * xv[4] + wb.y * xv[5] + wb.z * xv[6] + wb.w * xv[7]
                            + w8  * xv[8];
                }
            }
        }
    }

    if (active) {
#pragma unroll
        for (int k = 0; k < 9; k++) {
            float rx = (float)(k / 3 - 1);
            float ry = (float)(k % 3 - 1);
            float px = acc[k]     + rx + (float)(h + 1);
            float py = acc[9 + k] + ry + (float)(w + 1);
            float fx = floorf(px), fy = floorf(py);
            float ltx = fminf(fmaxf(fx,        0.f), 63.f);
            float lty = fminf(fmaxf(fy,        0.f), 63.f);
            float rbx = fminf(fmaxf(fx + 1.f,  0.f), 63.f);
            float rby = fminf(fmaxf(fy + 1.f,  0.f), 63.f);
            float pxc = fminf(fmaxf(px,        0.f), 63.f);
            float pyc = fminf(fmaxf(py,        0.f), 63.f);
            float glt = (1.f + (ltx - pxc)) * (1.f + (lty - pyc));
            float grb = (1.f - (rbx - pxc)) * (1.f - (rby - pyc));
            float glb = (1.f + (ltx - pxc)) * (1.f - (rby - pyc));
            float grt = (1.f - (rbx - pxc)) * (1.f + (lty - pyc));
            int iltx = (int)ltx, ilty = (int)lty, irbx = (int)rbx, irby = (int)rby;
            g_mw[pos * 9 + k] = make_float4(glt, grb, glb, grt);
            g_mi[pos * 9 + k] = make_int4(iltx * WW + ilty,
                                          irbx * WW + irby,
                                          iltx * WW + irby,
                                          irbx * WW + ilty);
        }
    }
}

// ---------------------------------------------------------------------------
// Kernel 2: implicit gather-GEMM, packed-fp32 (FFMA2), software-pipelined:
//   double-buffered sA/sB, one barrier per chunk.
//   B staged with cp.async (register-free), A prefetched via 32 LDGs + combine.
// ---------------------------------------------------------------------------
__global__ void __launch_bounds__(NTH, 2) main_kernel(const float* __restrict__ x,
                                                      float* __restrict__ out)
{
    extern __shared__ float smem[];
    float* sAb[2] = { smem, smem + KC * MT };
    float* sBb[2] = { smem + 2 * KC * MT, smem + 2 * KC * MT + KC * SB_STRIDE };

    const int tid = threadIdx.x;
    const int p0  = blockIdx.x * MT;  // all positions in one batch b, one row h
    const int b   = p0 >> 12;
    const float* xb = x + (size_t)b * CC * HWS;

    // ---- per-thread sampling metadata: 2 pairs, register-resident ----
    const int pA = tid, pB = tid + NTH;          // pair ids in [0,576)
    const int kA = pA >> 6, plA = pA & 63;
    const int kB = pB >> 6, plB = pB & 63;
    const float4 mwA = g_mw[(p0 + plA) * NP + kA];
    const int4   miA = g_mi[(p0 + plA) * NP + kA];
    const float4 mwB = g_mw[(p0 + plB) * NP + kB];
    const int4   miB = g_mi[(p0 + plB) * NP + kB];
    const int sAoffA = kA * MT + plA;            // sA[(cl*9+kA)*MT + plA]
    const int sAoffB = kB * MT + plB;

    const int tn4 = (tid & 31) * 4;
    const int tm  = (tid >> 5) & 7;
    const bool mathw = (tid < 256);

    unsigned long long acc_[8][4];
#pragma unroll
    for (int n = 0; n < 8; n++)
#pragma unroll
        for (int mp = 0; mp < 4; mp++) acc_[n][mp] = 0ull;

    // ---- prime chunk 0 ----
    {
#pragma unroll
        for (int r = 0; r < 8; r++) {
            int i  = tid + r * NTH;
            int kk = i >> 6;
            int o4 = (i & 63) << 2;
            cpa16(&sBb[0][kk * SB_STRIDE + o4], &g_wT[kk * OPL + o4]);
        }
        cpa_commit();
#pragma unroll
        for (int cl = 0; cl < CCK; cl++) {
            const float* xp = xb + cl * HWS;
            sAb[0][cl * (9 * MT) + sAoffA] =
                mwA.x * xp[miA.x] + mwA.y * xp[miA.y] + mwA.z * xp[miA.z] + mwA.w * xp[miA.w];
            sAb[0][cl * (9 * MT) + sAoffB] =
                mwB.x * xp[miB.x] + mwB.y * xp[miB.y] + mwB.z * xp[miB.z] + mwB.w * xp[miB.w];
        }
        cpa_wait();
    }
    __syncthreads();

    for (int c0 = 0; c0 < CC; c0 += CCK) {
        const int buf = (c0 / CCK) & 1;
        const float* sA = sAb[buf];
        const float* sB = sBb[buf];
        const int c1 = c0 + CCK;

        if (c1 < CC) {
            // ---- prefetch B(c1) via cp.async into other buffer ----
            float* sBn = sBb[buf ^ 1];
#pragma unroll
            for (int r = 0; r < 8; r++) {
                int i  = tid + r * NTH;
                int kk = i >> 6;
                int o4 = (i & 63) << 2;
                cpa16(&sBn[kk * SB_STRIDE + o4], &g_wT[(c1 * 9 + kk) * OPL + o4]);
            }
            cpa_commit();
            // ---- prefetch A(c1): 32 LDGs + combine + STS ----
            float* sAn = sAb[buf ^ 1];
            const float* xc = xb + c1 * HWS;
#pragma unroll
            for (int cl = 0; cl < CCK; cl++) {
                const float* xp = xc + cl * HWS;
                sAn[cl * (9 * MT) + sAoffA] =
                    mwA.x * xp[miA.x] + mwA.y * xp[miA.y] + mwA.z * xp[miA.z] + mwA.w * xp[miA.w];
                sAn[cl * (9 * MT) + sAoffB] =
                    mwB.x * xp[miB.x] + mwB.y * xp[miB.y] + mwB.z * xp[miB.z] + mwB.w * xp[miB.w];
            }
        }

        // ---- 64 x 256 x 36 packed-FMA block (warps 0-7) ----
        if (mathw) {
#pragma unroll 6
            for (int kk = 0; kk < KC; kk++) {
                const ulonglong2* pa = (const ulonglong2*)&sA[kk * MT + tm * 8];
                ulonglong2 a01 = pa[0];
                ulonglong2 a23 = pa[1];
                float4 b0 = *(const float4*)&sB[kk * SB_STRIDE + tn4];
                float4 b1 = *(const float4*)&sB[kk * SB_STRIDE + 128 + tn4];
                float bs[8] = {b0.x, b0.y, b0.z, b0.w, b1.x, b1.y, b1.z, b1.w};
#pragma unroll
                for (int n = 0; n < 8; n++) {
                    unsigned long long bd = dup2(bs[n]);
                    fma2(acc_[n][0], a01.x, bd);
                    fma2(acc_[n][1], a01.y, bd);
                    fma2(acc_[n][2], a23.x, bd);
                    fma2(acc_[n][3], a23.y, bd);
                }
            }
        }
        cpa_wait();
        __syncthreads();
    }

    // ---- epilogue: 8 consecutive hw per (thread, n) -> 2x STG.128 ----
    if (mathw) {
        const int hw0 = (p0 & 4095) + tm * 8;
        float* ob = out + (size_t)b * OPL * HWS;
#pragma unroll
        for (int g = 0; g < 2; g++) {
#pragma unroll
            for (int j = 0; j < 4; j++) {
                int n  = g * 128 + tn4 + j;
                int ai = g * 4 + j;
                UPair u0, u1, u2, u3;
                u0.u = acc_[ai][0]; u1.u = acc_[ai][1];
                u2.u = acc_[ai][2]; u3.u = acc_[ai][3];
                float4 v0 = make_float4(u0.f.x, u0.f.y, u1.f.x, u1.f.y);
                float4 v1 = make_float4(u2.f.x, u2.f.y, u3.f.x, u3.f.y);
                *(float4*)&ob[(size_t)n * HWS + hw0]     = v0;
                *(float4*)&ob[(size_t)n * HWS + hw0 + 4] = v1;
            }
        }
    }
}

// ---------------------------------------------------------------------------
extern "C" void kernel_launch(void* const* d_in, const int* in_sizes, int n_in,
                              void* d_out, int out_size)
{
    const float* x      = (const float*)d_in[0];   // (4,256,64,64)
    const float* w_p    = (const float*)d_in[1];   // (18,256,3,3)
    const float* w_conv = (const float*)d_in[2];   // (256,256,3,3)
    float* out = (float*)d_out;                    // (4,256,64,64)

    const int smem2 = (2 * KC * MT + 2 * KC * SB_STRIDE) * 4;   // 93,312 B
    static int configured = 0;
    cudaFuncSetAttribute(main_kernel, cudaFuncAttributeMaxDynamicSharedMemorySize, smem2);
    (void)configured;

    prep_kernel<<<128 + (KTOT * OPL + 255) / 256, 256>>>(x, w_p, w_conv);
    main_kernel<<<BB * HWS / MT, NTH, smem2>>>(x, out);
}

// round 8
// speedup vs baseline: 1.8403x; 1.8403x over previous
#include <cuda_runtime.h>
#include <cstdint>

#define BB   4
#define CC   256
#define HH   64
#define WW   64
#define HWS  4096
#define NP   9
#define OCH  18
#define OPL  256
#define KTOT 2304

#define MT     128        // GEMM M tile (positions per CTA)
#define NCHUNK 72         // K chunks of 32, kg' = k*256 + c ordering
#define NTH    256        // 8 warps: 2m x 4n warp grid, warp tile 64x64
#define AST    36         // sA row stride (floats)
#define BST    36         // sB row stride (floats)

// ---- dynamic smem layout for main kernel (bytes) ----
#define SM_MW   0                         // float4[128*9] = 18432
#define SM_MI   18432                     // int4  [128*9] = 18432
#define SM_A0   36864                     // 128 x 36 f32  = 18432
#define SM_A1   55296
#define SM_B0   73728                     // 256 x 36 f32  = 36864
#define SM_B1   110592
#define SM_TOTAL 147456

__device__ float4 g_mw[BB * HWS * NP];
__device__ int4   g_mi[BB * HWS * NP];
__device__ float  g_wB2[OPL * KTOT];   // [n][k*256+c], tf32-rounded

typedef unsigned long long ull;

// ---------------------------------------------------------------------------
// helpers
// ---------------------------------------------------------------------------
__device__ __forceinline__ float tf32r(float x) {
    uint32_t u;
    asm("cvt.rna.tf32.f32 %0, %1;" : "=r"(u) : "f"(x));
    return __uint_as_float(u);
}
__device__ __forceinline__ ull dup2(float v) {
    ull r; asm("mov.b64 %0, {%1, %1};" : "=l"(r) : "f"(v)); return r;
}
__device__ __forceinline__ ull pack2(float a, float b) {
    ull r; asm("mov.b64 %0, {%1, %2};" : "=l"(r) : "f"(a), "f"(b)); return r;
}
__device__ __forceinline__ void fma2(ull& acc, ull a, ull b) {
    asm("fma.rn.f32x2 %0, %1, %2, %0;" : "+l"(acc) : "l"(a), "l"(b));
}
union UPair { ull u; float2 f; };

__device__ __forceinline__ uint32_t smem_u32(const void* p) {
    return (uint32_t)__cvta_generic_to_shared(p);
}
__device__ __forceinline__ void cpa16(void* dst, const void* src) {
    asm volatile("cp.async.cg.shared.global [%0], [%1], 16;"
                 :: "r"(smem_u32(dst)), "l"(src));
}
__device__ __forceinline__ void cpa_wait() { asm volatile("cp.async.wait_all;" ::: "memory"); }

__device__ __forceinline__ void mma_tf32(float* c, const uint32_t* a, const uint32_t* b) {
    asm volatile(
        "mma.sync.aligned.m16n8k8.row.col.f32.tf32.tf32.f32 "
        "{%0,%1,%2,%3}, {%4,%5,%6,%7}, {%8,%9}, {%0,%1,%2,%3};"
        : "+f"(c[0]), "+f"(c[1]), "+f"(c[2]), "+f"(c[3])
        : "r"(a[0]), "r"(a[1]), "r"(a[2]), "r"(a[3]), "r"(b[0]), "r"(b[1]));
}

__device__ __forceinline__ float dot4(float4 wv, const float* xp, int4 iv) {
    return wv.x * xp[iv.x] + wv.y * xp[iv.y] + wv.z * xp[iv.z] + wv.w * xp[iv.w];
}

// ---------------------------------------------------------------------------
// Kernel 1 (fused prep):
//   blocks [0,128):    offset conv (3x3, C=256->18) + sampling metadata
//                      512 threads, 4-way channel split, packed f32x2 FMA
//   blocks [128,1280): permute+tf32-round w_conv -> g_wB2[n][k*256+c]
// ---------------------------------------------------------------------------
__global__ __launch_bounds__(512) void prep_kernel(const float* __restrict__ x,
                                                   const float* __restrict__ w_p,
                                                   const float* __restrict__ wc)
{
    if (blockIdx.x >= 128) {
        int idx = (blockIdx.x - 128) * 512 + threadIdx.x;
        if (idx < OPL * KTOT) {
            int n = idx / KTOT;
            int r = idx - n * KTOT;
            int k = r >> 8;
            int c = r & 255;
            g_wB2[idx] = tf32r(wc[n * KTOT + c * 9 + k]);
        }
        return;
    }

    // union: s_w2 [64][9][10] ull (46080 B)  /  s_red [4][128][9] ull (36864 B)
    __shared__ ull s_mem[64 * 9 * 10];

    const int tid   = threadIdx.x;
    const int pos_l = tid & 127;
    const int part  = tid >> 7;                 // 0..3: channel quarter
    const int pos   = blockIdx.x * 128 + pos_l;
    const int b = pos >> 12;
    const int h = (pos >> 6) & 63;
    const int w = pos & 63;
    const float* xb = x + (size_t)b * CC * HWS;

    ull accp[9];
#pragma unroll
    for (int i = 0; i < 9; i++) accp[i] = 0ull;

    for (int blk = 0; blk < 4; blk++) {
        __syncthreads();
        // stage packed weight pairs for this 64-channel block
        for (int i = tid; i < 64 * 81; i += 512) {
            int cl = i / 81;
            int r  = i - cl * 81;
            int t  = r / 9;
            int op = r - t * 9;
            int c  = blk * 64 + cl;
            float w0 = w_p[((2 * op)     * CC + c) * 9 + t];
            float w1 = w_p[((2 * op + 1) * CC + c) * 9 + t];
            s_mem[(cl * 9 + t) * 10 + op] = pack2(w0, w1);
        }
        __syncthreads();

        for (int q = 0; q < 16; q++) {
            int cl = part * 16 + q;
            const float* xp = xb + (size_t)(blk * 64 + cl) * HWS;
            float xv[9];
#pragma unroll
            for (int dh = -1; dh <= 1; dh++) {
#pragma unroll
                for (int dw = -1; dw <= 1; dw++) {
                    int hh = h + dh, ww = w + dw;
                    float v = 0.f;
                    if (hh >= 0 && hh < HH && ww >= 0 && ww < WW) v = xp[hh * WW + ww];
                    xv[(dh + 1) * 3 + (dw + 1)] = v;
                }
            }
#pragma unroll
            for (int t = 0; t < 9; t++) {
                ull xd = dup2(xv[t]);
                const ull* wp2 = &s_mem[(cl * 9 + t) * 10];
#pragma unroll
                for (int op = 0; op < 9; op++) fma2(accp[op], wp2[op], xd);
            }
        }
    }

    __syncthreads();     // done reading s_w2; reuse as s_red
    ull* s_red = s_mem;  // [part][pos_l][9]
#pragma unroll
    for (int op = 0; op < 9; op++)
        s_red[(part * 128 + pos_l) * 9 + op] = accp[op];
    __syncthreads();

    if (tid < 128) {
        float acc[OCH];
#pragma unroll
        for (int op = 0; op < 9; op++) {
            UPair u0, u1, u2, u3;
            u0.u = s_red[(0 * 128 + tid) * 9 + op];
            u1.u = s_red[(1 * 128 + tid) * 9 + op];
            u2.u = s_red[(2 * 128 + tid) * 9 + op];
            u3.u = s_red[(3 * 128 + tid) * 9 + op];
            acc[2 * op]     = u0.f.x + u1.f.x + u2.f.x + u3.f.x;
            acc[2 * op + 1] = u0.f.y + u1.f.y + u2.f.y + u3.f.y;
        }
#pragma unroll
        for (int k = 0; k < 9; k++) {
            float rx = (float)(k / 3 - 1);
            float ry = (float)(k % 3 - 1);
            float px = acc[k]     + rx + (float)(h + 1);
            float py = acc[9 + k] + ry + (float)(w + 1);
            float fx = floorf(px), fy = floorf(py);
            float ltx = fminf(fmaxf(fx,       0.f), 63.f);
            float lty = fminf(fmaxf(fy,       0.f), 63.f);
            float rbx = fminf(fmaxf(fx + 1.f, 0.f), 63.f);
            float rby = fminf(fmaxf(fy + 1.f, 0.f), 63.f);
            float pxc = fminf(fmaxf(px,       0.f), 63.f);
            float pyc = fminf(fmaxf(py,       0.f), 63.f);
            float glt = (1.f + (ltx - pxc)) * (1.f + (lty - pyc));
            float grb = (1.f - (rbx - pxc)) * (1.f - (rby - pyc));
            float glb = (1.f + (ltx - pxc)) * (1.f - (rby - pyc));
            float grt = (1.f - (rbx - pxc)) * (1.f + (lty - pyc));
            int iltx = (int)ltx, ilty = (int)lty, irbx = (int)rbx, irby = (int)rby;
            g_mw[pos * 9 + k] = make_float4(glt, grb, glb, grt);
            g_mi[pos * 9 + k] = make_int4(iltx * WW + ilty,
                                          irbx * WW + irby,
                                          iltx * WW + irby,
                                          irbx * WW + ilty);
        }
    }
}

// ---------------------------------------------------------------------------
// Kernel 2: mma.sync tf32 gather-GEMM
//   M=128 positions, N=256, K=2304 in 72 chunks of 32 (one kernel-point per
//   chunk). Double-buffered smem, cp.async B, warp tile 64x64 (m16n8k8).
// ---------------------------------------------------------------------------
__global__ void __launch_bounds__(NTH, 1) main_kernel(const float* __restrict__ x,
                                                      float* __restrict__ out)
{
    extern __shared__ char smem[];
    float4* sMW = (float4*)(smem + SM_MW);
    int4*   sMI = (int4*)(smem + SM_MI);
    float*  sAb[2] = { (float*)(smem + SM_A0), (float*)(smem + SM_A1) };
    float*  sBb[2] = { (float*)(smem + SM_B0), (float*)(smem + SM_B1) };

    const int tid  = threadIdx.x;
    const int wid  = tid >> 5;
    const int lane = tid & 31;
    const int gid  = lane >> 2;        // 0..7
    const int tig  = lane & 3;         // 0..3
    const int p0   = blockIdx.x * MT;
    const int b    = p0 >> 12;
    const float* xb = x + (size_t)b * CC * HWS;

    // gather ids: 2 threads per position, 16 channels each
    const int posl = tid & 127;
    const int half = tid >> 7;         // 0 or 1

    // math ids: warp grid 2m x 4n
    const int mBase = (wid & 1) * 64;
    const int nBase = (wid >> 1) * 64;

    // stage metadata once
    for (int i = tid; i < MT * NP; i += NTH) {
        sMW[i] = g_mw[p0 * NP + i];
        sMI[i] = g_mi[p0 * NP + i];
    }
    __syncthreads();

    float acc[4][8][4];
#pragma unroll
    for (int mf = 0; mf < 4; mf++)
#pragma unroll
        for (int nf = 0; nf < 8; nf++)
#pragma unroll
            for (int r = 0; r < 4; r++) acc[mf][nf][r] = 0.f;

    // ---- prime chunk 0 ----
    {
        const float* src = g_wB2 + (size_t)tid * KTOT;       // row n = tid
        float* sb = sBb[0] + tid * BST;
#pragma unroll
        for (int q = 0; q < 8; q++) cpa16(sb + q * 4, src + q * 4);

        const int c0 = half << 4;
        float4 wv = sMW[posl * NP];
        int4   iv = sMI[posl * NP];
        float* sa = sAb[0] + posl * AST + (half << 4);
#pragma unroll
        for (int g = 0; g < 4; g++) {
            const float* x0 = xb + (size_t)(c0 + g * 4) * HWS;
            float4 v;
            v.x = tf32r(dot4(wv, x0,           iv));
            v.y = tf32r(dot4(wv, x0 + HWS,     iv));
            v.z = tf32r(dot4(wv, x0 + 2 * HWS, iv));
            v.w = tf32r(dot4(wv, x0 + 3 * HWS, iv));
            *(float4*)(sa + g * 4) = v;
        }
        cpa_wait();
    }
    __syncthreads();

    for (int i = 0; i < NCHUNK; i++) {
        const int bf = i & 1;

        if (i + 1 < NCHUNK) {
            // ---- prefetch B(i+1) via cp.async ----
            const float* src = g_wB2 + (size_t)tid * KTOT + (i + 1) * 32;
            float* sb = sBb[bf ^ 1] + tid * BST;
#pragma unroll
            for (int q = 0; q < 8; q++) cpa16(sb + q * 4, src + q * 4);

            // ---- gather A(i+1): 16 bilinear samples, tf32 ----
            const int k  = (i + 1) >> 3;
            const int c0 = (((i + 1) & 7) << 5) + (half << 4);
            float4 wv = sMW[posl * NP + k];
            int4   iv = sMI[posl * NP + k];
            float* sa = sAb[bf ^ 1] + posl * AST + (half << 4);
#pragma unroll
            for (int g = 0; g < 4; g++) {
                const float* x0 = xb + (size_t)(c0 + g * 4) * HWS;
                float4 v;
                v.x = tf32r(dot4(wv, x0,           iv));
                v.y = tf32r(dot4(wv, x0 + HWS,     iv));
                v.z = tf32r(dot4(wv, x0 + 2 * HWS, iv));
                v.w = tf32r(dot4(wv, x0 + 3 * HWS, iv));
                *(float4*)(sa + g * 4) = v;
            }
        }

        // ---- math: 128 x 256 x 32 via m16n8k8 ----
        {
            const uint32_t* sAu = (const uint32_t*)sAb[bf];
            const uint32_t* sBu = (const uint32_t*)sBb[bf];
#pragma unroll
            for (int ks = 0; ks < 4; ks++) {
                const int k0 = ks * 8 + tig;
                uint32_t a[4][4], bfrag[8][2];
#pragma unroll
                for (int mf = 0; mf < 4; mf++) {
                    int m = mBase + mf * 16 + gid;
                    a[mf][0] = sAu[m * AST + k0];
                    a[mf][1] = sAu[(m + 8) * AST + k0];
                    a[mf][2] = sAu[m * AST + k0 + 4];
                    a[mf][3] = sAu[(m + 8) * AST + k0 + 4];
                }
#pragma unroll
                for (int nf = 0; nf < 8; nf++) {
                    int n = nBase + nf * 8 + gid;
                    bfrag[nf][0] = sBu[n * BST + k0];
                    bfrag[nf][1] = sBu[n * BST + k0 + 4];
                }
#pragma unroll
                for (int mf = 0; mf < 4; mf++)
#pragma unroll
                    for (int nf = 0; nf < 8; nf++)
                        mma_tf32(acc[mf][nf], a[mf], bfrag[nf]);
            }
        }

        cpa_wait();
        __syncthreads();
    }

    // ---- epilogue: fragments -> out[n][hw] ----
    {
        const int hw0 = p0 & 4095;
        float* ob = out + (size_t)b * OPL * HWS + hw0;
#pragma unroll
        for (int mf = 0; mf < 4; mf++) {
            int m = mBase + mf * 16 + gid;
#pragma unroll
            for (int nf = 0; nf < 8; nf++) {
                int n = nBase + nf * 8 + 2 * tig;
                ob[(size_t)n * HWS + m]           = acc[mf][nf][0];
                ob[(size_t)(n + 1) * HWS + m]     = acc[mf][nf][1];
                ob[(size_t)n * HWS + m + 8]       = acc[mf][nf][2];
                ob[(size_t)(n + 1) * HWS + m + 8] = acc[mf][nf][3];
            }
        }
    }
}

// ---------------------------------------------------------------------------
extern "C" void kernel_launch(void* const* d_in, const int* in_sizes, int n_in,
                              void* d_out, int out_size)
{
    const float* x      = (const float*)d_in[0];   // (4,256,64,64)
    const float* w_p    = (const float*)d_in[1];   // (18,256,3,3)
    const float* w_conv = (const float*)d_in[2];   // (256,256,3,3)
    float* out = (float*)d_out;                    // (4,256,64,64)

    cudaFuncSetAttribute(main_kernel, cudaFuncAttributeMaxDynamicSharedMemorySize, SM_TOTAL);

    const int permBlocks = (OPL * KTOT + 511) / 512;
    prep_kernel<<<128 + permBlocks, 512>>>(x, w_p, w_conv);
    main_kernel<<<BB * HWS / MT, NTH, SM_TOTAL>>>(x, out);
}

// round 9
// speedup vs baseline: 1.9471x; 1.0580x over previous
#include <cuda_runtime.h>
#include <cstdint>

#define BB   4
#define CC   256
#define HH   64
#define WW   64
#define HWS  4096
#define NP   9
#define OCH  18
#define OPL  256
#define KTOT 2304

#define MT     128        // GEMM M tile (positions per CTA)
#define NCHUNK 72         // K chunks of 32, kg' = k*256 + c ordering
#define NTH    512        // 16 warps: 4m x 4n warp grid, warp tile 32x64
#define AST    36         // sA row stride (floats)
#define BST    36         // sB row stride (floats)

// ---- dynamic smem layout for main kernel (bytes) ----
#define SM_MW   0                         // float4[128*9] = 18432
#define SM_MI   18432                     // int4  [128*9] = 18432
#define SM_A0   36864                     // 128 x 36 f32  = 18432
#define SM_A1   55296
#define SM_B0   73728                     // 256 x 36 f32  = 36864
#define SM_B1   110592
#define SM_TOTAL 147456

__device__ float4 g_mw[BB * HWS * NP];
__device__ int4   g_mi[BB * HWS * NP];
__device__ float  g_wB2[OPL * KTOT];   // [n][k*256+c], tf32-rounded

typedef unsigned long long ull;

// ---------------------------------------------------------------------------
// helpers
// ---------------------------------------------------------------------------
__device__ __forceinline__ float tf32r(float x) {
    uint32_t u;
    asm("cvt.rna.tf32.f32 %0, %1;" : "=r"(u) : "f"(x));
    return __uint_as_float(u);
}
__device__ __forceinline__ ull dup2(float v) {
    ull r; asm("mov.b64 %0, {%1, %1};" : "=l"(r) : "f"(v)); return r;
}
__device__ __forceinline__ ull pack2(float a, float b) {
    ull r; asm("mov.b64 %0, {%1, %2};" : "=l"(r) : "f"(a), "f"(b)); return r;
}
__device__ __forceinline__ void fma2(ull& acc, ull a, ull b) {
    asm("fma.rn.f32x2 %0, %1, %2, %0;" : "+l"(acc) : "l"(a), "l"(b));
}
union UPair { ull u; float2 f; };

__device__ __forceinline__ uint32_t smem_u32(const void* p) {
    return (uint32_t)__cvta_generic_to_shared(p);
}
__device__ __forceinline__ void cpa16(void* dst, const void* src) {
    asm volatile("cp.async.cg.shared.global [%0], [%1], 16;"
                 :: "r"(smem_u32(dst)), "l"(src));
}
__device__ __forceinline__ void cpa_wait() { asm volatile("cp.async.wait_all;" ::: "memory"); }

__device__ __forceinline__ void mma_tf32(float* c, const uint32_t* a, const uint32_t* b) {
    asm volatile(
        "mma.sync.aligned.m16n8k8.row.col.f32.tf32.tf32.f32 "
        "{%0,%1,%2,%3}, {%4,%5,%6,%7}, {%8,%9}, {%0,%1,%2,%3};"
        : "+f"(c[0]), "+f"(c[1]), "+f"(c[2]), "+f"(c[3])
        : "r"(a[0]), "r"(a[1]), "r"(a[2]), "r"(a[3]), "r"(b[0]), "r"(b[1]));
}

__device__ __forceinline__ float dot4(float4 wv, const float* xp, int4 iv) {
    return wv.x * xp[iv.x] + wv.y * xp[iv.y] + wv.z * xp[iv.z] + wv.w * xp[iv.w];
}

// ---------------------------------------------------------------------------
// Kernel 1 (fused prep):
//   blocks [0,128):    offset conv (3x3, C=256->18) + sampling metadata
//                      512 threads, 4-way channel split, packed f32x2 FMA,
//                      vectorized (LDS.128) weight fetch
//   blocks [128,1280): permute+tf32-round w_conv -> g_wB2[n][k*256+c]
// ---------------------------------------------------------------------------
__global__ __launch_bounds__(512) void prep_kernel(const float* __restrict__ x,
                                                   const float* __restrict__ w_p,
                                                   const float* __restrict__ wc)
{
    if (blockIdx.x >= 128) {
        int idx = (blockIdx.x - 128) * 512 + threadIdx.x;
        if (idx < OPL * KTOT) {
            int n = idx / KTOT;
            int r = idx - n * KTOT;
            int k = r >> 8;
            int c = r & 255;
            g_wB2[idx] = tf32r(wc[n * KTOT + c * 9 + k]);
        }
        return;
    }

    // union: s_w2 [64][9][10] ull (46080 B)  /  s_red [4][128][9] ull (36864 B)
    __shared__ ull s_mem[64 * 9 * 10];

    const int tid   = threadIdx.x;
    const int pos_l = tid & 127;
    const int part  = tid >> 7;                 // 0..3: channel quarter
    const int pos   = blockIdx.x * 128 + pos_l;
    const int b = pos >> 12;
    const int h = (pos >> 6) & 63;
    const int w = pos & 63;
    const float* xb = x + (size_t)b * CC * HWS;

    ull accp[9];
#pragma unroll
    for (int i = 0; i < 9; i++) accp[i] = 0ull;

    for (int blk = 0; blk < 4; blk++) {
        __syncthreads();
        // stage packed weight pairs for this 64-channel block
        for (int i = tid; i < 64 * 81; i += 512) {
            int cl = i / 81;
            int r  = i - cl * 81;
            int t  = r / 9;
            int op = r - t * 9;
            int c  = blk * 64 + cl;
            float w0 = w_p[((2 * op)     * CC + c) * 9 + t];
            float w1 = w_p[((2 * op + 1) * CC + c) * 9 + t];
            s_mem[(cl * 9 + t) * 10 + op] = pack2(w0, w1);
        }
        __syncthreads();

        for (int q = 0; q < 16; q++) {
            int cl = part * 16 + q;
            const float* xp = xb + (size_t)(blk * 64 + cl) * HWS;
            float xv[9];
#pragma unroll
            for (int dh = -1; dh <= 1; dh++) {
#pragma unroll
                for (int dw = -1; dw <= 1; dw++) {
                    int hh = h + dh, ww = w + dw;
                    float v = 0.f;
                    if (hh >= 0 && hh < HH && ww >= 0 && ww < WW) v = xp[hh * WW + ww];
                    xv[(dh + 1) * 3 + (dw + 1)] = v;
                }
            }
#pragma unroll
            for (int t = 0; t < 9; t++) {
                ull xd = dup2(xv[t]);
                const ulonglong2* wp4 = (const ulonglong2*)&s_mem[(cl * 9 + t) * 10];
                ulonglong2 p01 = wp4[0];
                ulonglong2 p23 = wp4[1];
                ulonglong2 p45 = wp4[2];
                ulonglong2 p67 = wp4[3];
                ull p8 = s_mem[(cl * 9 + t) * 10 + 8];
                fma2(accp[0], p01.x, xd);
                fma2(accp[1], p01.y, xd);
                fma2(accp[2], p23.x, xd);
                fma2(accp[3], p23.y, xd);
                fma2(accp[4], p45.x, xd);
                fma2(accp[5], p45.y, xd);
                fma2(accp[6], p67.x, xd);
                fma2(accp[7], p67.y, xd);
                fma2(accp[8], p8,    xd);
            }
        }
    }

    __syncthreads();     // done reading s_w2; reuse as s_red
    ull* s_red = s_mem;  // [part][pos_l][9]
#pragma unroll
    for (int op = 0; op < 9; op++)
        s_red[(part * 128 + pos_l) * 9 + op] = accp[op];
    __syncthreads();

    if (tid < 128) {
        float acc[OCH];
#pragma unroll
        for (int op = 0; op < 9; op++) {
            UPair u0, u1, u2, u3;
            u0.u = s_red[(0 * 128 + tid) * 9 + op];
            u1.u = s_red[(1 * 128 + tid) * 9 + op];
            u2.u = s_red[(2 * 128 + tid) * 9 + op];
            u3.u = s_red[(3 * 128 + tid) * 9 + op];
            acc[2 * op]     = u0.f.x + u1.f.x + u2.f.x + u3.f.x;
            acc[2 * op + 1] = u0.f.y + u1.f.y + u2.f.y + u3.f.y;
        }
#pragma unroll
        for (int k = 0; k < 9; k++) {
            float rx = (float)(k / 3 - 1);
            float ry = (float)(k % 3 - 1);
            float px = acc[k]     + rx + (float)(h + 1);
            float py = acc[9 + k] + ry + (float)(w + 1);
            float fx = floorf(px), fy = floorf(py);
            float ltx = fminf(fmaxf(fx,       0.f), 63.f);
            float lty = fminf(fmaxf(fy,       0.f), 63.f);
            float rbx = fminf(fmaxf(fx + 1.f, 0.f), 63.f);
            float rby = fminf(fmaxf(fy + 1.f, 0.f), 63.f);
            float pxc = fminf(fmaxf(px,       0.f), 63.f);
            float pyc = fminf(fmaxf(py,       0.f), 63.f);
            float glt = (1.f + (ltx - pxc)) * (1.f + (lty - pyc));
            float grb = (1.f - (rbx - pxc)) * (1.f - (rby - pyc));
            float glb = (1.f + (ltx - pxc)) * (1.f - (rby - pyc));
            float grt = (1.f - (rbx - pxc)) * (1.f + (lty - pyc));
            int iltx = (int)ltx, ilty = (int)lty, irbx = (int)rbx, irby = (int)rby;
            g_mw[pos * 9 + k] = make_float4(glt, grb, glb, grt);
            g_mi[pos * 9 + k] = make_int4(iltx * WW + ilty,
                                          irbx * WW + irby,
                                          iltx * WW + irby,
                                          irbx * WW + ilty);
        }
    }
}

// ---------------------------------------------------------------------------
// Kernel 2: mma.sync tf32 gather-GEMM, 512 threads
//   M=128 positions, N=256, K=2304 in 72 chunks of 32 (one kernel-point per
//   chunk). Warp grid 4m x 4n, warp tile 32x64. Double-buffered smem,
//   cp.async B stage, software-pipelined A gather.
// ---------------------------------------------------------------------------
__global__ void __launch_bounds__(NTH, 1) main_kernel(const float* __restrict__ x,
                                                      float* __restrict__ out)
{
    extern __shared__ char smem[];
    float4* sMW = (float4*)(smem + SM_MW);
    int4*   sMI = (int4*)(smem + SM_MI);
    float*  sAb[2] = { (float*)(smem + SM_A0), (float*)(smem + SM_A1) };
    float*  sBb[2] = { (float*)(smem + SM_B0), (float*)(smem + SM_B1) };

    const int tid  = threadIdx.x;
    const int wid  = tid >> 5;
    const int lane = tid & 31;
    const int gid  = lane >> 2;        // 0..7
    const int tig  = lane & 3;         // 0..3
    const int p0   = blockIdx.x * MT;
    const int b    = p0 >> 12;
    const float* xb = x + (size_t)b * CC * HWS;

    // gather ids: 4 threads per position, 8 channels each
    const int posl = tid & 127;
    const int cq   = tid >> 7;         // 0..3 channel-quarter of the 32-chunk

    // B-stage ids: 2 threads per row, 16 floats each
    const int brow = tid >> 1;
    const int bhalf = (tid & 1) << 4;

    // math ids: warp grid 4m x 4n, warp tile 32x64
    const int mBase = (wid & 3) * 32;
    const int nBase = (wid >> 2) * 64;

    // stage metadata once
    for (int i = tid; i < MT * NP; i += NTH) {
        sMW[i] = g_mw[p0 * NP + i];
        sMI[i] = g_mi[p0 * NP + i];
    }
    __syncthreads();

    float acc[2][8][4];
#pragma unroll
    for (int mf = 0; mf < 2; mf++)
#pragma unroll
        for (int nf = 0; nf < 8; nf++)
#pragma unroll
            for (int r = 0; r < 4; r++) acc[mf][nf][r] = 0.f;

    // ---- prime chunk 0 ----
    {
        const float* src = g_wB2 + (size_t)brow * KTOT + bhalf;
        float* sb = sBb[0] + brow * BST + bhalf;
#pragma unroll
        for (int q = 0; q < 4; q++) cpa16(sb + q * 4, src + q * 4);

        float4 wv = sMW[posl * NP];
        int4   iv = sMI[posl * NP];
        const float* xc = xb + (size_t)(cq * 8) * HWS;
        float* sa = sAb[0] + posl * AST + cq * 8;
#pragma unroll
        for (int g = 0; g < 2; g++) {
            const float* x0 = xc + (size_t)(g * 4) * HWS;
            float4 v;
            v.x = tf32r(dot4(wv, x0,           iv));
            v.y = tf32r(dot4(wv, x0 + HWS,     iv));
            v.z = tf32r(dot4(wv, x0 + 2 * HWS, iv));
            v.w = tf32r(dot4(wv, x0 + 3 * HWS, iv));
            *(float4*)(sa + g * 4) = v;
        }
        cpa_wait();
    }
    __syncthreads();

    for (int i = 0; i < NCHUNK; i++) {
        const int bf = i & 1;

        if (i + 1 < NCHUNK) {
            // ---- prefetch B(i+1) via cp.async ----
            const float* src = g_wB2 + (size_t)brow * KTOT + (i + 1) * 32 + bhalf;
            float* sb = sBb[bf ^ 1] + brow * BST + bhalf;
#pragma unroll
            for (int q = 0; q < 4; q++) cpa16(sb + q * 4, src + q * 4);

            // ---- gather A(i+1): 8 bilinear samples, tf32 ----
            const int k  = (i + 1) >> 3;
            const int c0 = (((i + 1) & 7) << 5) + cq * 8;
            float4 wv = sMW[posl * NP + k];
            int4   iv = sMI[posl * NP + k];
            const float* xc = xb + (size_t)c0 * HWS;
            float* sa = sAb[bf ^ 1] + posl * AST + cq * 8;
#pragma unroll
            for (int g = 0; g < 2; g++) {
                const float* x0 = xc + (size_t)(g * 4) * HWS;
                float4 v;
                v.x = tf32r(dot4(wv, x0,           iv));
                v.y = tf32r(dot4(wv, x0 + HWS,     iv));
                v.z = tf32r(dot4(wv, x0 + 2 * HWS, iv));
                v.w = tf32r(dot4(wv, x0 + 3 * HWS, iv));
                *(float4*)(sa + g * 4) = v;
            }
        }

        // ---- math: 128 x 256 x 32 via m16n8k8, warp tile 32x64 ----
        {
            const uint32_t* sAu = (const uint32_t*)sAb[bf];
            const uint32_t* sBu = (const uint32_t*)sBb[bf];
#pragma unroll
            for (int ks = 0; ks < 4; ks++) {
                const int k0 = ks * 8 + tig;
                uint32_t a[2][4], bfrag[8][2];
#pragma unroll
                for (int mf = 0; mf < 2; mf++) {
                    int m = mBase + mf * 16 + gid;
                    a[mf][0] = sAu[m * AST + k0];
                    a[mf][1] = sAu[(m + 8) * AST + k0];
                    a[mf][2] = sAu[m * AST + k0 + 4];
                    a[mf][3] = sAu[(m + 8) * AST + k0 + 4];
                }
#pragma unroll
                for (int nf = 0; nf < 8; nf++) {
                    int n = nBase + nf * 8 + gid;
                    bfrag[nf][0] = sBu[n * BST + k0];
                    bfrag[nf][1] = sBu[n * BST + k0 + 4];
                }
#pragma unroll
                for (int mf = 0; mf < 2; mf++)
#pragma unroll
                    for (int nf = 0; nf < 8; nf++)
                        mma_tf32(acc[mf][nf], a[mf], bfrag[nf]);
            }
        }

        cpa_wait();
        __syncthreads();
    }

    // ---- epilogue: fragments -> out[n][hw] ----
    {
        const int hw0 = p0 & 4095;
        float* ob = out + (size_t)b * OPL * HWS + hw0;
#pragma unroll
        for (int mf = 0; mf < 2; mf++) {
            int m = mBase + mf * 16 + gid;
#pragma unroll
            for (int nf = 0; nf < 8; nf++) {
                int n = nBase + nf * 8 + 2 * tig;
                ob[(size_t)n * HWS + m]           = acc[mf][nf][0];
                ob[(size_t)(n + 1) * HWS + m]     = acc[mf][nf][1];
                ob[(size_t)n * HWS + m + 8]       = acc[mf][nf][2];
                ob[(size_t)(n + 1) * HWS + m + 8] = acc[mf][nf][3];
            }
        }
    }
}

// ---------------------------------------------------------------------------
extern "C" void kernel_launch(void* const* d_in, const int* in_sizes, int n_in,
                              void* d_out, int out_size)
{
    const float* x      = (const float*)d_in[0];   // (4,256,64,64)
    const float* w_p    = (const float*)d_in[1];   // (18,256,3,3)
    const float* w_conv = (const float*)d_in[2];   // (256,256,3,3)
    float* out = (float*)d_out;                    // (4,256,64,64)

    cudaFuncSetAttribute(main_kernel, cudaFuncAttributeMaxDynamicSharedMemorySize, SM_TOTAL);

    const int permBlocks = (OPL * KTOT + 511) / 512;
    prep_kernel<<<128 + permBlocks, 512>>>(x, w_p, w_conv);
    main_kernel<<<BB * HWS / MT, NTH, SM_TOTAL>>>(x, out);
}

// round 10
// speedup vs baseline: 2.2809x; 1.1715x over previous
#include <cuda_runtime.h>
#include <cstdint>

#define BB   4
#define CC   256
#define HH   64
#define WW   64
#define HWS  4096
#define NP   9
#define OCH  18
#define OPL  256
#define KTOT 2304
#define MTOT 16384        // B*H*W

#define MT     128        // GEMM M tile
#define NCHUNK 72         // K chunks of 32, kg' = k*256 + c ordering
#define NTH    512
#define MST    136        // sA row stride (floats), K-major: bank = 8*tig+gid
#define BST    36         // sB row stride (floats)
#define NSTAGE 3

// ---- dynamic smem for GEMM: 3 x (A 32x136 + B 256x36) ----
#define SA_BYTES (32 * MST * 4)            // 17408
#define SB_BYTES (256 * BST * 4)           // 36864
#define SM_SB0   (NSTAGE * SA_BYTES)       // 52224
#define SM_TOTAL (NSTAGE * (SA_BYTES + SB_BYTES))   // 162816

__device__ float4 g_mw[BB * HWS * NP];
__device__ int4   g_mi[BB * HWS * NP];
__device__ float  g_wB2[OPL * KTOT];       // [n][k*256+c], tf32-rounded
__device__ float  g_A[(size_t)KTOT * MTOT];// A^T: [kg'][pos], tf32 gathered samples

typedef unsigned long long ull;

// ---------------------------------------------------------------------------
// helpers
// ---------------------------------------------------------------------------
__device__ __forceinline__ float tf32r(float x) {
    uint32_t u;
    asm("cvt.rna.tf32.f32 %0, %1;" : "=r"(u) : "f"(x));
    return __uint_as_float(u);
}
__device__ __forceinline__ ull dup2(float v) {
    ull r; asm("mov.b64 %0, {%1, %1};" : "=l"(r) : "f"(v)); return r;
}
__device__ __forceinline__ ull pack2(float a, float b) {
    ull r; asm("mov.b64 %0, {%1, %2};" : "=l"(r) : "f"(a), "f"(b)); return r;
}
__device__ __forceinline__ void fma2(ull& acc, ull a, ull b) {
    asm("fma.rn.f32x2 %0, %1, %2, %0;" : "+l"(acc) : "l"(a), "l"(b));
}
union UPair { ull u; float2 f; };

__device__ __forceinline__ uint32_t smem_u32(const void* p) {
    return (uint32_t)__cvta_generic_to_shared(p);
}
__device__ __forceinline__ void cpa16(void* dst, const void* src) {
    asm volatile("cp.async.cg.shared.global [%0], [%1], 16;"
                 :: "r"(smem_u32(dst)), "l"(src));
}
__device__ __forceinline__ void cpa_commit() {
    asm volatile("cp.async.commit_group;" ::: "memory");
}
template <int N>
__device__ __forceinline__ void cpa_wait_group() {
    asm volatile("cp.async.wait_group %0;" :: "n"(N) : "memory");
}

__device__ __forceinline__ void mma_tf32(float* c, const uint32_t* a, const uint32_t* b) {
    asm volatile(
        "mma.sync.aligned.m16n8k8.row.col.f32.tf32.tf32.f32 "
        "{%0,%1,%2,%3}, {%4,%5,%6,%7}, {%8,%9}, {%0,%1,%2,%3};"
        : "+f"(c[0]), "+f"(c[1]), "+f"(c[2]), "+f"(c[3])
        : "r"(a[0]), "r"(a[1]), "r"(a[2]), "r"(a[3]), "r"(b[0]), "r"(b[1]));
}

__device__ __forceinline__ float dot4(float4 wv, const float* xp, int4 iv) {
    return wv.x * xp[iv.x] + wv.y * xp[iv.y] + wv.z * xp[iv.z] + wv.w * xp[iv.w];
}

// ---------------------------------------------------------------------------
// Kernel 1 (fused prep): offsets conv + metadata (blocks 0..127),
//                        w_conv permute+tf32 (blocks 128+)
// ---------------------------------------------------------------------------
__global__ __launch_bounds__(512) void prep_kernel(const float* __restrict__ x,
                                                   const float* __restrict__ w_p,
                                                   const float* __restrict__ wc)
{
    if (blockIdx.x >= 128) {
        int idx = (blockIdx.x - 128) * 512 + threadIdx.x;
        if (idx < OPL * KTOT) {
            int n = idx / KTOT;
            int r = idx - n * KTOT;
            int k = r >> 8;
            int c = r & 255;
            g_wB2[idx] = tf32r(wc[n * KTOT + c * 9 + k]);
        }
        return;
    }

    __shared__ ull s_mem[64 * 9 * 10];

    const int tid   = threadIdx.x;
    const int pos_l = tid & 127;
    const int part  = tid >> 7;
    const int pos   = blockIdx.x * 128 + pos_l;
    const int b = pos >> 12;
    const int h = (pos >> 6) & 63;
    const int w = pos & 63;
    const float* xb = x + (size_t)b * CC * HWS;

    ull accp[9];
#pragma unroll
    for (int i = 0; i < 9; i++) accp[i] = 0ull;

    for (int blk = 0; blk < 4; blk++) {
        __syncthreads();
        for (int i = tid; i < 64 * 81; i += 512) {
            int cl = i / 81;
            int r  = i % 81;
            int t  = r / 9;
            int op = r - t * 9;
            int c  = blk * 64 + cl;
            float w0 = w_p[((2 * op)     * CC + c) * 9 + t];
            float w1 = w_p[((2 * op + 1) * CC + c) * 9 + t];
            s_mem[(cl * 9 + t) * 10 + op] = pack2(w0, w1);
        }
        __syncthreads();

        for (int q = 0; q < 16; q++) {
            int cl = part * 16 + q;
            const float* xp = xb + (size_t)(blk * 64 + cl) * HWS;
            float xv[9];
#pragma unroll
            for (int dh = -1; dh <= 1; dh++) {
#pragma unroll
                for (int dw = -1; dw <= 1; dw++) {
                    int hh = h + dh, ww = w + dw;
                    float v = 0.f;
                    if (hh >= 0 && hh < HH && ww >= 0 && ww < WW) v = xp[hh * WW + ww];
                    xv[(dh + 1) * 3 + (dw + 1)] = v;
                }
            }
#pragma unroll
            for (int t = 0; t < 9; t++) {
                ull xd = dup2(xv[t]);
                const ulonglong2* wp4 = (const ulonglong2*)&s_mem[(cl * 9 + t) * 10];
                ulonglong2 p01 = wp4[0];
                ulonglong2 p23 = wp4[1];
                ulonglong2 p45 = wp4[2];
                ulonglong2 p67 = wp4[3];
                ull p8 = s_mem[(cl * 9 + t) * 10 + 8];
                fma2(accp[0], p01.x, xd);
                fma2(accp[1], p01.y, xd);
                fma2(accp[2], p23.x, xd);
                fma2(accp[3], p23.y, xd);
                fma2(accp[4], p45.x, xd);
                fma2(accp[5], p45.y, xd);
                fma2(accp[6], p67.x, xd);
                fma2(accp[7], p67.y, xd);
                fma2(accp[8], p8,    xd);
            }
        }
    }

    __syncthreads();
    ull* s_red = s_mem;
#pragma unroll
    for (int op = 0; op < 9; op++)
        s_red[(part * 128 + pos_l) * 9 + op] = accp[op];
    __syncthreads();

    if (tid < 128) {
        float acc[OCH];
#pragma unroll
        for (int op = 0; op < 9; op++) {
            UPair u0, u1, u2, u3;
            u0.u = s_red[(0 * 128 + tid) * 9 + op];
            u1.u = s_red[(1 * 128 + tid) * 9 + op];
            u2.u = s_red[(2 * 128 + tid) * 9 + op];
            u3.u = s_red[(3 * 128 + tid) * 9 + op];
            acc[2 * op]     = u0.f.x + u1.f.x + u2.f.x + u3.f.x;
            acc[2 * op + 1] = u0.f.y + u1.f.y + u2.f.y + u3.f.y;
        }
#pragma unroll
        for (int k = 0; k < 9; k++) {
            float rx = (float)(k / 3 - 1);
            float ry = (float)(k % 3 - 1);
            float px = acc[k]     + rx + (float)(h + 1);
            float py = acc[9 + k] + ry + (float)(w + 1);
            float fx = floorf(px), fy = floorf(py);
            float ltx = fminf(fmaxf(fx,       0.f), 63.f);
            float lty = fminf(fmaxf(fy,       0.f), 63.f);
            float rbx = fminf(fmaxf(fx + 1.f, 0.f), 63.f);
            float rby = fminf(fmaxf(fy + 1.f, 0.f), 63.f);
            float pxc = fminf(fmaxf(px,       0.f), 63.f);
            float pyc = fminf(fmaxf(py,       0.f), 63.f);
            float glt = (1.f + (ltx - pxc)) * (1.f + (lty - pyc));
            float grb = (1.f - (rbx - pxc)) * (1.f - (rby - pyc));
            float glb = (1.f + (ltx - pxc)) * (1.f - (rby - pyc));
            float grt = (1.f - (rbx - pxc)) * (1.f + (lty - pyc));
            int iltx = (int)ltx, ilty = (int)lty, irbx = (int)rbx, irby = (int)rby;
            g_mw[pos * 9 + k] = make_float4(glt, grb, glb, grt);
            g_mi[pos * 9 + k] = make_int4(iltx * WW + ilty,
                                          irbx * WW + irby,
                                          iltx * WW + irby,
                                          irbx * WW + ilty);
        }
    }
}

// ---------------------------------------------------------------------------
// Kernel 2: gather — materialize A^T[kg'][pos] (tf32 bilinear samples)
//   128 blocks x 1024 threads. warp -> (pos-window pw, channel-slice cs).
//   lane -> consecutive pos: coalesced loads AND stores. No barriers.
// ---------------------------------------------------------------------------
__global__ __launch_bounds__(1024) void gather_kernel(const float* __restrict__ x)
{
    const int tid  = threadIdx.x;
    const int warp = tid >> 5;
    const int lane = tid & 31;
    const int pw   = warp & 3;         // pos window 0..3
    const int cs   = warp >> 2;        // channel slice 0..7 (32 ch each)
    const int pos  = blockIdx.x * 128 + pw * 32 + lane;
    const int b    = pos >> 12;
    const float* xb = x + (size_t)b * CC * HWS;

#pragma unroll
    for (int k = 0; k < 9; k++) {
        const float4 wv = g_mw[pos * NP + k];
        const int4   iv = g_mi[pos * NP + k];
        const int kg0 = k * 256 + cs * 32;
        float* op = g_A + (size_t)kg0 * MTOT + pos;
        const float* xp = xb + (size_t)(cs * 32) * HWS;
#pragma unroll 8
        for (int j = 0; j < 32; j++) {
            op[(size_t)j * MTOT] = tf32r(dot4(wv, xp + (size_t)j * HWS, iv));
        }
    }
}

// ---------------------------------------------------------------------------
// Kernel 3: dense tf32 GEMM, 3-stage cp.async pipeline
//   out[n][m] = sum_kg A^T[kg][m] * B[n][kg].  M tile 128, N 256, k chunk 32.
//   A smem K-major [32][136] (conflict-free frags), B [256][36].
// ---------------------------------------------------------------------------
__global__ void __launch_bounds__(NTH, 1) gemm_kernel(float* __restrict__ out)
{
    extern __shared__ char smem[];

    const int tid  = threadIdx.x;
    const int wid  = tid >> 5;
    const int lane = tid & 31;
    const int gid  = lane >> 2;
    const int tig  = lane & 3;
    const int p0   = blockIdx.x * MT;
    const int b    = p0 >> 12;
    const int m0   = p0;               // column offset in A^T rows

    const int mBase = (wid & 3) * 32;
    const int nBase = (wid >> 2) * 64;

    // copy-task ids
    const int aRow = tid >> 5;         // with r: id = tid + r*512 -> row=id>>5 (0..31), q=id&31
    const int bRow0 = tid >> 3;        // id>>3, q = id&7

    auto issue_stage = [&](int i, int s) {
        char* sa = smem + s * SA_BYTES;
        char* sb = smem + SM_SB0 + s * SB_BYTES;
        const size_t kg0 = (size_t)i * 32;
        // A: 32 rows x 128 floats
#pragma unroll
        for (int r = 0; r < 2; r++) {
            int id = tid + r * NTH;
            int kr = id >> 5;
            int q  = id & 31;
            cpa16(sa + kr * (MST * 4) + q * 16,
                  g_A + (kg0 + kr) * MTOT + m0 + q * 4);
        }
        // B: 256 rows x 32 floats
#pragma unroll
        for (int r = 0; r < 4; r++) {
            int id = tid + r * NTH;
            int nr = id >> 3;
            int q  = id & 7;
            cpa16(sb + nr * (BST * 4) + q * 16,
                  g_wB2 + (size_t)nr * KTOT + kg0 + q * 4);
        }
        cpa_commit();
    };

    float acc[2][8][4];
#pragma unroll
    for (int mf = 0; mf < 2; mf++)
#pragma unroll
        for (int nf = 0; nf < 8; nf++)
#pragma unroll
            for (int r = 0; r < 4; r++) acc[mf][nf][r] = 0.f;

    issue_stage(0, 0);
    issue_stage(1, 1);

    for (int i = 0; i < NCHUNK; i++) {
        const int s = i % NSTAGE;
        cpa_wait_group<1>();
        __syncthreads();

        if (i + 2 < NCHUNK) issue_stage(i + 2, (i + 2) % NSTAGE);
        else                cpa_commit();   // keep group accounting aligned

        const uint32_t* sAu = (const uint32_t*)(smem + s * SA_BYTES);
        const uint32_t* sBu = (const uint32_t*)(smem + SM_SB0 + s * SB_BYTES);
#pragma unroll
        for (int ks = 0; ks < 4; ks++) {
            const int kr0 = ks * 8 + tig;       // A^T row within chunk
            uint32_t a[2][4], bfrag[8][2];
#pragma unroll
            for (int mf = 0; mf < 2; mf++) {
                int m = mBase + mf * 16 + gid;
                a[mf][0] = sAu[kr0 * MST + m];
                a[mf][1] = sAu[kr0 * MST + m + 8];
                a[mf][2] = sAu[(kr0 + 4) * MST + m];
                a[mf][3] = sAu[(kr0 + 4) * MST + m + 8];
            }
#pragma unroll
            for (int nf = 0; nf < 8; nf++) {
                int n = nBase + nf * 8 + gid;
                bfrag[nf][0] = sBu[n * BST + ks * 8 + tig];
                bfrag[nf][1] = sBu[n * BST + ks * 8 + tig + 4];
            }
#pragma unroll
            for (int mf = 0; mf < 2; mf++)
#pragma unroll
                for (int nf = 0; nf < 8; nf++)
                    mma_tf32(acc[mf][nf], a[mf], bfrag[nf]);
        }
    }

    // ---- epilogue: fragments -> out[n][hw] ----
    {
        const int hw0 = p0 & 4095;
        float* ob = out + (size_t)b * OPL * HWS + hw0;
#pragma unroll
        for (int mf = 0; mf < 2; mf++) {
            int m = mBase + mf * 16 + gid;
#pragma unroll
            for (int nf = 0; nf < 8; nf++) {
                int n = nBase + nf * 8 + 2 * tig;
                ob[(size_t)n * HWS + m]           = acc[mf][nf][0];
                ob[(size_t)(n + 1) * HWS + m]     = acc[mf][nf][1];
                ob[(size_t)n * HWS + m + 8]       = acc[mf][nf][2];
                ob[(size_t)(n + 1) * HWS + m + 8] = acc[mf][nf][3];
            }
        }
    }
}

// ---------------------------------------------------------------------------
extern "C" void kernel_launch(void* const* d_in, const int* in_sizes, int n_in,
                              void* d_out, int out_size)
{
    const float* x      = (const float*)d_in[0];   // (4,256,64,64)
    const float* w_p    = (const float*)d_in[1];   // (18,256,3,3)
    const float* w_conv = (const float*)d_in[2];   // (256,256,3,3)
    float* out = (float*)d_out;                    // (4,256,64,64)

    cudaFuncSetAttribute(gemm_kernel, cudaFuncAttributeMaxDynamicSharedMemorySize, SM_TOTAL);

    const int permBlocks = (OPL * KTOT + 511) / 512;
    prep_kernel<<<128 + permBlocks, 512>>>(x, w_p, w_conv);
    gather_kernel<<<MTOT / 128, 1024>>>(x);
    gemm_kernel<<<MTOT / MT, NTH, SM_TOTAL>>>(out);
}